// round 5
// baseline (speedup 1.0000x reference)
#include <cuda_runtime.h>
#include <cuda_fp16.h>

#define NMAX 100000
#define EMAX 3200000
#define NG 64
#define NC 10
#define SCANB 1024

// ---------------- device scratch ----------------
__device__ int gcn_is64;
__device__ int gcn_degi[NMAX];          // in-degree (without self loop)
__device__ int gcn_off[NMAX + 1];       // CSR row offsets (by dst)
__device__ int gcn_cur[NMAX];           // fill cursors
__device__ int gcn_blocksum[128];
__device__ __align__(16) int gcn_csrc[EMAX];   // CSR column (src) indices
__device__ int gcn_batch[NMAX];
__device__ float gcn_dinv[NMAX];
__device__ __align__(16) uint4 gcn_bufA[NMAX];  // 6 halves packed per node (16B)
__device__ __align__(16) uint4 gcn_bufB[NMAX];
__device__ float gcn_pool[NG * NC];
__device__ float gcn_cnt[NG];

__device__ __forceinline__ uint4 pack6(const float* o) {
    uint4 r;
    __half2 h01 = __floats2half2_rn(o[0], o[1]);
    __half2 h23 = __floats2half2_rn(o[2], o[3]);
    __half2 h45 = __floats2half2_rn(o[4], o[5]);
    r.x = *(unsigned*)&h01;
    r.y = *(unsigned*)&h23;
    r.z = *(unsigned*)&h45;
    r.w = 0u;
    return r;
}

__device__ __forceinline__ void unpack_add(uint4 v, float* a) {
    float2 f0 = __half22float2(*(__half2*)&v.x);
    float2 f1 = __half22float2(*(__half2*)&v.y);
    float2 f2 = __half22float2(*(__half2*)&v.z);
    a[0] += f0.x; a[1] += f0.y; a[2] += f1.x; a[3] += f1.y; a[4] += f2.x; a[5] += f2.y;
}

// half2-native CSR row walk (4 threads/node, stride 4, dual accumulator banks).
// Returns fp32 partials in a[6].
__device__ __forceinline__ void row_accum_h2(const uint4* __restrict__ vin,
                                             int base, int end, int q, float* a) {
    __half2 z = __float2half2_rn(0.0f);
    __half2 c0a = z, c1a = z, c2a = z;
    __half2 c0b = z, c1b = z, c2b = z;
    int e = base + q;
#pragma unroll 1
    for (; e + 4 < end; e += 8) {
        int s0 = gcn_csrc[e];
        int s1 = gcn_csrc[e + 4];
        uint4 v0 = __ldg(&vin[s0]);
        uint4 v1 = __ldg(&vin[s1]);
        c0a = __hadd2(c0a, *(__half2*)&v0.x);
        c1a = __hadd2(c1a, *(__half2*)&v0.y);
        c2a = __hadd2(c2a, *(__half2*)&v0.z);
        c0b = __hadd2(c0b, *(__half2*)&v1.x);
        c1b = __hadd2(c1b, *(__half2*)&v1.y);
        c2b = __hadd2(c2b, *(__half2*)&v1.z);
    }
    if (e < end) {
        uint4 v = __ldg(&vin[gcn_csrc[e]]);
        c0a = __hadd2(c0a, *(__half2*)&v.x);
        c1a = __hadd2(c1a, *(__half2*)&v.y);
        c2a = __hadd2(c2a, *(__half2*)&v.z);
    }
    float2 f0a = __half22float2(c0a), f0b = __half22float2(c0b);
    float2 f1a = __half22float2(c1a), f1b = __half22float2(c1b);
    float2 f2a = __half22float2(c2a), f2b = __half22float2(c2b);
    a[0] = f0a.x + f0b.x; a[1] = f0a.y + f0b.y;
    a[2] = f1a.x + f1b.x; a[3] = f1a.y + f1b.y;
    a[4] = f2a.x + f2b.x; a[5] = f2a.y + f2b.y;
}

// ---------------- init ----------------
__global__ __launch_bounds__(256) void k_init(int N) {
    int i = blockIdx.x * 256 + threadIdx.x;
    if (i < N) gcn_degi[i] = 0;
    if (i < NG) gcn_cnt[i] = 0.0f;
    if (i < NG * NC) gcn_pool[i] = 0.0f;
}

// ---------------- dtype detection: int32 vs int64 indices ----------------
__global__ void k_detect(const void* edge, int N) {
    const long long* p = (const long long*)edge;
    int bad = 0;
    for (int t = threadIdx.x; t < 128; t += 32) {
        long long v = p[t];
        if (v < 0 || v >= (long long)N) bad = 1;
    }
    bad = __any_sync(0xffffffffu, bad);
    if (threadIdx.x == 0) gcn_is64 = bad ? 0 : 1;
}

// ---------------- degree histogram + batch counts (4 edges/thread) ----------
__global__ __launch_bounds__(256) void k_hist(const void* edge, const void* batchp,
                                              int N, int E) {
    int i = blockIdx.x * 256 + threadIdx.x;
    int is64 = gcn_is64;
    int i4 = i * 4;
    if (i4 + 3 < E) {
        int d0, d1, d2, d3;
        if (is64) {
            const longlong2* dp = (const longlong2*)((const long long*)edge + E);
            longlong2 p0 = __ldg(&dp[i * 2]);
            longlong2 p1 = __ldg(&dp[i * 2 + 1]);
            d0 = (int)p0.x; d1 = (int)p0.y; d2 = (int)p1.x; d3 = (int)p1.y;
        } else {
            int4 p = __ldg(&((const int4*)((const int*)edge + E))[i]);
            d0 = p.x; d1 = p.y; d2 = p.z; d3 = p.w;
        }
        atomicAdd(&gcn_degi[d0], 1);
        atomicAdd(&gcn_degi[d1], 1);
        atomicAdd(&gcn_degi[d2], 1);
        atomicAdd(&gcn_degi[d3], 1);
    } else {
        for (int e = i4; e < E; e++) {
            int d = is64 ? (int)((const long long*)edge)[(size_t)E + e]
                         : ((const int*)edge)[(size_t)E + e];
            atomicAdd(&gcn_degi[d], 1);
        }
    }
    if (i < N) {
        int b = is64 ? (int)((const long long*)batchp)[i] : ((const int*)batchp)[i];
        gcn_batch[i] = b;
        atomicAdd(&gcn_cnt[b], 1.0f);
    }
}

// ---------------- 3-phase exclusive scan of degi -> off ----------------
__global__ __launch_bounds__(SCANB) void k_scan1(int N) {
    __shared__ int s[SCANB];
    int t = threadIdx.x;
    int i = blockIdx.x * SCANB + t;
    int v = (i < N) ? gcn_degi[i] : 0;
    s[t] = v;
    __syncthreads();
    for (int d = 1; d < SCANB; d <<= 1) {
        int x = (t >= d) ? s[t - d] : 0;
        __syncthreads();
        s[t] += x;
        __syncthreads();
    }
    if (i < N) gcn_off[i] = s[t] - v;   // exclusive (local)
    if (t == SCANB - 1) gcn_blocksum[blockIdx.x] = s[t];
}

__global__ void k_scan2(int nblk) {
    __shared__ int s[128];
    int t = threadIdx.x;
    int v = (t < nblk) ? gcn_blocksum[t] : 0;
    s[t] = v;
    __syncthreads();
    for (int d = 1; d < 128; d <<= 1) {
        int x = (t >= d) ? s[t - d] : 0;
        __syncthreads();
        s[t] += x;
        __syncthreads();
    }
    if (t < nblk) gcn_blocksum[t] = s[t] - v;  // exclusive block bases
}

__global__ __launch_bounds__(256) void k_scan3(int N, int E) {
    int i = blockIdx.x * 256 + threadIdx.x;
    if (i < N) {
        int o = gcn_off[i] + gcn_blocksum[i >> 10];
        gcn_off[i] = o;
        gcn_cur[i] = o;
    }
    if (i == 0) gcn_off[N] = E;
}

// ---------------- CSR fill (counting sort, 4 edges/thread) ----------------
__global__ __launch_bounds__(256) void k_fill(const void* edge, int E) {
    int i = blockIdx.x * 256 + threadIdx.x;
    int is64 = gcn_is64;
    int i4 = i * 4;
    if (i4 + 3 < E) {
        int s0, s1, s2, s3, d0, d1, d2, d3;
        if (is64) {
            const longlong2* sp = (const longlong2*)edge;
            const longlong2* dp = (const longlong2*)((const long long*)edge + E);
            longlong2 a0 = __ldg(&sp[i * 2]), a1 = __ldg(&sp[i * 2 + 1]);
            longlong2 b0 = __ldg(&dp[i * 2]), b1 = __ldg(&dp[i * 2 + 1]);
            s0 = (int)a0.x; s1 = (int)a0.y; s2 = (int)a1.x; s3 = (int)a1.y;
            d0 = (int)b0.x; d1 = (int)b0.y; d2 = (int)b1.x; d3 = (int)b1.y;
        } else {
            int4 a = __ldg(&((const int4*)edge)[i]);
            int4 b = __ldg(&((const int4*)((const int*)edge + E))[i]);
            s0 = a.x; s1 = a.y; s2 = a.z; s3 = a.w;
            d0 = b.x; d1 = b.y; d2 = b.z; d3 = b.w;
        }
        gcn_csrc[atomicAdd(&gcn_cur[d0], 1)] = s0;
        gcn_csrc[atomicAdd(&gcn_cur[d1], 1)] = s1;
        gcn_csrc[atomicAdd(&gcn_cur[d2], 1)] = s2;
        gcn_csrc[atomicAdd(&gcn_cur[d3], 1)] = s3;
    } else {
        for (int e = i4; e < E; e++) {
            int s, d;
            if (is64) {
                s = (int)((const long long*)edge)[e];
                d = (int)((const long long*)edge)[(size_t)E + e];
            } else {
                s = ((const int*)edge)[e];
                d = ((const int*)edge)[(size_t)E + e];
            }
            gcn_csrc[atomicAdd(&gcn_cur[d], 1)] = s;
        }
    }
}

// ---------------- layer-1 transform: bufA = fp16( (x @ W1) * dinv ) ----------
__global__ __launch_bounds__(256) void k_mm1(const float* __restrict__ x,
                                             const float* __restrict__ W, int N) {
    __shared__ float sW[128 * 8];
    for (int t = threadIdx.x; t < 1024; t += 256) {
        int k = t >> 3, j = t & 7;
        sW[t] = (j < 6) ? W[k * 6 + j] : 0.0f;
    }
    __syncthreads();
    int g = blockIdx.x * 256 + threadIdx.x;
    int i = g >> 2;
    int q = g & 3;
    if (i >= N) return;
    const float4* xr = (const float4*)(x + (size_t)i * 128) + q * 8;
    float a[6];
#pragma unroll
    for (int j = 0; j < 6; j++) a[j] = 0.0f;
#pragma unroll
    for (int k4 = 0; k4 < 8; k4++) {
        float4 xv = xr[k4];
        const float* wp = &sW[(q * 8 + k4) * 32];
#pragma unroll
        for (int j = 0; j < 6; j++) {
            a[j] += xv.x * wp[j] + xv.y * wp[8 + j] + xv.z * wp[16 + j] + xv.w * wp[24 + j];
        }
    }
#pragma unroll
    for (int j = 0; j < 6; j++) {
        a[j] += __shfl_xor_sync(0xffffffffu, a[j], 1);
        a[j] += __shfl_xor_sync(0xffffffffu, a[j], 2);
    }
    if (q == 0) {
        float dinv = rsqrtf((float)(gcn_degi[i] + 1));   // +1: self loop
        gcn_dinv[i] = dinv;
        float o[6] = { a[0] * dinv, a[1] * dinv, a[2] * dinv,
                       a[3] * dinv, a[4] * dinv, a[5] * dinv };
        gcn_bufA[i] = pack6(o);
    }
}

// ---------------- fused CSR aggregation (4 threads/node, half2) + GEMM -------
template <bool APPLY_W>
__global__ __launch_bounds__(256) void k_csr(const uint4* __restrict__ vin,
                                             uint4* __restrict__ vout,
                                             const float* __restrict__ b,
                                             const float* __restrict__ W, int N) {
    __shared__ float sW[48];
    __shared__ float sb[6];
    if (threadIdx.x < 48) {
        int k = threadIdx.x >> 3, j = threadIdx.x & 7;
        sW[threadIdx.x] = (APPLY_W && j < 6) ? W[k * 6 + j] : 0.0f;
    }
    if (threadIdx.x < 6) sb[threadIdx.x] = b[threadIdx.x];
    __syncthreads();
    int g = blockIdx.x * 256 + threadIdx.x;
    int i = g >> 2;
    int q = g & 3;
    bool valid = (i < N);
    int base = 0, end = 0;
    if (valid) { base = gcn_off[i]; end = gcn_off[i + 1]; }

    float a[6];
    row_accum_h2(vin, base, end, q, a);

#pragma unroll
    for (int j = 0; j < 6; j++) {
        a[j] += __shfl_xor_sync(0xffffffffu, a[j], 1);
        a[j] += __shfl_xor_sync(0xffffffffu, a[j], 2);
    }
    if (!valid || q != 0) return;

    unpack_add(__ldg(&vin[i]), a);       // self loop (fp32 add)
    float dinv = gcn_dinv[i];
    float h[6];
#pragma unroll
    for (int j = 0; j < 6; j++) h[j] = fmaxf(dinv * a[j] + sb[j], 0.0f);
    float o[6];
    if (APPLY_W) {
#pragma unroll
        for (int j = 0; j < 6; j++) {
            float s = 0.0f;
#pragma unroll
            for (int k = 0; k < 6; k++) s += h[k] * sW[k * 8 + j];
            o[j] = s * dinv;
        }
    } else {
#pragma unroll
        for (int j = 0; j < 6; j++) o[j] = h[j] * dinv;
    }
    vout[i] = pack6(o);
}

// ---------------- final: CSR agg (half2) + (agg @ Wf + bf) relu + pool -------
__global__ __launch_bounds__(256) void k_csr_final(const uint4* __restrict__ vin,
                                                   const float* __restrict__ Wf,
                                                   const float* __restrict__ bf, int N) {
    __shared__ float sW[60];
    __shared__ float sb[10];
    __shared__ float sp[NG * NC];
    for (int t = threadIdx.x; t < NG * NC; t += 256) sp[t] = 0.0f;
    if (threadIdx.x < 60) sW[threadIdx.x] = Wf[threadIdx.x];
    if (threadIdx.x < 10) sb[threadIdx.x] = bf[threadIdx.x];
    __syncthreads();
    int g = blockIdx.x * 256 + threadIdx.x;
    int i = g >> 2;
    int q = g & 3;
    bool valid = (i < N);
    int base = 0, end = 0;
    if (valid) { base = gcn_off[i]; end = gcn_off[i + 1]; }

    float a[6];
    row_accum_h2(vin, base, end, q, a);
#pragma unroll
    for (int j = 0; j < 6; j++) {
        a[j] += __shfl_xor_sync(0xffffffffu, a[j], 1);
        a[j] += __shfl_xor_sync(0xffffffffu, a[j], 2);
    }
    if (valid && q == 0) {
        unpack_add(__ldg(&vin[i]), a);
        float dinv = gcn_dinv[i];
#pragma unroll
        for (int j = 0; j < 6; j++) a[j] *= dinv;
        int bg = gcn_batch[i];
#pragma unroll
        for (int c = 0; c < 10; c++) {
            float s = sb[c];
#pragma unroll
            for (int j = 0; j < 6; j++) s += a[j] * sW[j * 10 + c];
            s = fmaxf(s, 0.0f);
            atomicAdd(&sp[bg * 10 + c], s);
        }
    }
    __syncthreads();
    int first = blockIdx.x * 64;           // 64 nodes per block (4 threads each)
    if (first >= N) return;
    int last = min(first + 63, N - 1);
    int bmin = gcn_batch[first], bmax = gcn_batch[last];   // batch sorted
    int cnt = (bmax - bmin + 1) * 10;
    for (int t = threadIdx.x; t < cnt; t += 256) {
        float v = sp[bmin * 10 + t];
        if (v != 0.0f) atomicAdd(&gcn_pool[bmin * 10 + t], v);
    }
}

// ---------------- mean + log_softmax ----------------
__global__ void k_out(float* __restrict__ out) {
    int g = threadIdx.x;
    if (g >= NG) return;
    float cnt = fmaxf(gcn_cnt[g], 1.0f);
    float p[10];
    float m = -1e30f;
#pragma unroll
    for (int c = 0; c < 10; c++) {
        p[c] = gcn_pool[g * 10 + c] / cnt;
        m = fmaxf(m, p[c]);
    }
    float s = 0.0f;
#pragma unroll
    for (int c = 0; c < 10; c++) s += expf(p[c] - m);
    float l = logf(s);
#pragma unroll
    for (int c = 0; c < 10; c++) out[g * 10 + c] = p[c] - m - l;
}

// ---------------- launch ----------------
extern "C" void kernel_launch(void* const* d_in, const int* in_sizes, int n_in,
                              void* d_out, int out_size) {
    const float* x     = (const float*)d_in[0];
    const void*  edge  = d_in[1];
    const void*  batch = d_in[2];
    const float* W1 = (const float*)d_in[3];
    const float* b1 = (const float*)d_in[4];
    const float* W2 = (const float*)d_in[5];
    const float* b2 = (const float*)d_in[6];
    const float* W3 = (const float*)d_in[7];
    const float* b3 = (const float*)d_in[8];
    const float* W4 = (const float*)d_in[9];
    const float* b4 = (const float*)d_in[10];
    const float* W5 = (const float*)d_in[11];
    const float* b5 = (const float*)d_in[12];
    const float* W6 = (const float*)d_in[13];
    const float* b6 = (const float*)d_in[14];
    const float* Wf = (const float*)d_in[15];
    const float* bf = (const float*)d_in[16];

    int N = in_sizes[0] / 128;
    int E = in_sizes[1] / 2;
    float* out = (float*)d_out;

    int nb_n  = (N + 255) / 256;
    int nb_e4 = ((E + 3) / 4 + 255) / 256;
    int nb_s  = (N + SCANB - 1) / SCANB;
    int nb_m  = (4 * N + 255) / 256;   // 4 threads per node

    void* pA; void* pB;
    cudaGetSymbolAddress(&pA, gcn_bufA);
    cudaGetSymbolAddress(&pB, gcn_bufB);
    uint4* A  = (uint4*)pA;
    uint4* Bv = (uint4*)pB;

    k_init<<<nb_n, 256>>>(N);
    k_detect<<<1, 32>>>(edge, N);
    k_hist<<<nb_e4, 256>>>(edge, batch, N, E);
    k_scan1<<<nb_s, SCANB>>>(N);
    k_scan2<<<1, 128>>>(nb_s);
    k_scan3<<<nb_n, 256>>>(N, E);
    k_fill<<<nb_e4, 256>>>(edge, E);

    k_mm1<<<nb_m, 256>>>(x, W1, N);                        // -> A (g1)
    k_csr<true><<<nb_m, 256>>>(A, Bv, b1, W2, N);          // -> B (g2)
    k_csr<true><<<nb_m, 256>>>(Bv, A, b2, W3, N);          // -> A (g3)
    k_csr<true><<<nb_m, 256>>>(A, Bv, b3, W4, N);          // -> B (g4)
    k_csr<true><<<nb_m, 256>>>(Bv, A, b4, W5, N);          // -> A (g5)
    k_csr<true><<<nb_m, 256>>>(A, Bv, b5, W6, N);          // -> B (g6)
    k_csr<false><<<nb_m, 256>>>(Bv, A, b6, nullptr, N);    // -> A (h6*dinv)
    k_csr_final<<<nb_m, 256>>>(A, Wf, bf, N);
    k_out<<<1, 64>>>(out);
}